// round 13
// baseline (speedup 1.0000x reference)
#include <cuda_runtime.h>
#include <cuda_bf16.h>
#include <cstdint>

#define NN 50000
#define EE 100000
#define CC 256
#define NW_WORDS 1568
#define EW_WORDS 3125
#define INF_I 0x7FFFFFFF
#define IDXM 131071
#define ROUNDS 9
#define SCAN_BLOCKS 196
#define MEGA_BLOCKS 112

// GEMM tiling
#define AS_STRIDE 144            // 72 bf16 per smem row (64 + 8 pad) -> conflict-free ldmatrix
#define PLANE 18432              // 128 rows * 144 B
#define SMEM_GEMM (4 * PLANE)    // Ah, Al, Bh, Bl = 73728 B

// ---------------- scratch (static device globals; no allocation) -------------
__device__ float g_xt[NN * CC];
__device__ __nv_bfloat16 g_xh[NN * CC];     // x split hi
__device__ __nv_bfloat16 g_xl[NN * CC];     // x split lo
__device__ __nv_bfloat16 g_Wh2[CC * CC];    // W split hi, [n][k] row-major
__device__ __nv_bfloat16 g_Wl2[CC * CC];    // W split lo
__device__ int   g_deg[NN];
__device__ int   g_off[NN + 1];
__device__ int   g_cur[NN];
__device__ int   g_srclist[EE];
__device__ int   g_mask[NN];
__device__ int   g_bsum[SCAN_BLOCKS];

// merge state
__device__ int      g_minFS[NN];
__device__ int      g_minFT[NN];
__device__ int      g_mUS[NN];
__device__ int      g_mUT[NN];
__device__ unsigned g_disc0[NW_WORDS];
__device__ unsigned g_und[EW_WORDS];
__device__ int      g_wl[2][EE];
__device__ int      g_cnt[2];
__device__ int      g_bar;

// ---------------- mma helpers -------------------------------------------------
__device__ __forceinline__ uint32_t smem_u32(const void* p) {
    uint32_t a;
    asm("{ .reg .u64 t; cvta.to.shared.u64 t, %1; cvt.u32.u64 %0, t; }" : "=r"(a) : "l"(p));
    return a;
}
__device__ __forceinline__ void ldmx4(uint32_t* r, uint32_t addr) {
    asm volatile("ldmatrix.sync.aligned.m8n8.x4.shared.b16 {%0,%1,%2,%3}, [%4];"
                 : "=r"(r[0]), "=r"(r[1]), "=r"(r[2]), "=r"(r[3]) : "r"(addr));
}
__device__ __forceinline__ void ldmx2(uint32_t* r, uint32_t addr) {
    asm volatile("ldmatrix.sync.aligned.m8n8.x2.shared.b16 {%0,%1}, [%2];"
                 : "=r"(r[0]), "=r"(r[1]) : "r"(addr));
}
__device__ __forceinline__ void mma_bf16(float* c, const uint32_t* a, const uint32_t* b) {
    asm volatile(
        "mma.sync.aligned.m16n8k16.row.col.f32.bf16.bf16.f32 "
        "{%0,%1,%2,%3}, {%4,%5,%6,%7}, {%8,%9}, {%0,%1,%2,%3};"
        : "+f"(c[0]), "+f"(c[1]), "+f"(c[2]), "+f"(c[3])
        : "r"(a[0]), "r"(a[1]), "r"(a[2]), "r"(a[3]), "r"(b[0]), "r"(b[1]));
}

// ---------------- fused init + W split ----------------------------------------
__global__ void init_prep_kernel(const float* __restrict__ W) {
    int i = blockIdx.x * blockDim.x + threadIdx.x;   // 65536 threads
    if (i < NN) {
        g_minFS[i] = INF_I;
        g_minFT[i] = INF_I;
        g_mUS[i] = 0;
        g_mUT[i] = 0;
        g_deg[i] = 0;
    }
    if (i < NW_WORDS) g_disc0[i] = 0u;
    if (i < EW_WORDS) g_und[i] = 0u;
    if (i == 0) { g_cnt[0] = 0; g_cnt[1] = 0; g_bar = 0; }
    {
        float w = W[i];                               // W[n][k], i = n*256+k
        __nv_bfloat16 hi = __float2bfloat16_rn(w);
        __nv_bfloat16 lo = __float2bfloat16_rn(w - __bfloat162float(hi));
        g_Wh2[i] = hi;
        g_Wl2[i] = lo;
    }
}

// ---------------- x split: fp32 -> bf16 hi/lo ----------------------------------
__global__ void xsplit_kernel(const float* __restrict__ x) {
    int i = blockIdx.x * blockDim.x + threadIdx.x;   // NN*CC/4 threads
    if (i >= NN * CC / 4) return;
    float4 v = reinterpret_cast<const float4*>(x)[i];
    float f[4] = {v.x, v.y, v.z, v.w};
    __nv_bfloat16 h[4], l[4];
#pragma unroll
    for (int q = 0; q < 4; q++) {
        h[q] = __float2bfloat16_rn(f[q]);
        l[q] = __float2bfloat16_rn(f[q] - __bfloat162float(h[q]));
    }
    reinterpret_cast<uint2*>(g_xh)[i] = *reinterpret_cast<uint2*>(h);
    reinterpret_cast<uint2*>(g_xl)[i] = *reinterpret_cast<uint2*>(l);
}

// ---------------- GEMM: xt = x @ W^T + b  (mma.sync bf16 split, 3 passes) -----
__global__ __launch_bounds__(256, 2)
void gemm_mma_kernel(const float* __restrict__ bias, int M) {
    extern __shared__ char sm[];
    const uint32_t sb = smem_u32(sm);
    const int tid = threadIdx.x;
    const int warp = tid >> 5;
    const int lane = tid & 31;
    const int m0 = blockIdx.x * 128;
    const int n0 = blockIdx.y * 128;
    const int wrow = (warp & 3) * 32;    // 4 warps down M
    const int wcol = (warp >> 2) * 64;   // 2 warps across N

    float acc[16][4];
#pragma unroll
    for (int t = 0; t < 16; t++)
#pragma unroll
        for (int q = 0; q < 4; q++) acc[t][q] = 0.f;

    const int crow = tid >> 1;
    const int chalf = tid & 1;
    int arow_g = m0 + crow;
    if (arow_g >= M) arow_g = M - 1;
    const int brow_g = n0 + crow;

    const uint32_t a_base = sb + (uint32_t)(wrow + (lane & 15)) * AS_STRIDE + (lane >> 4) * 16;
    const int lb = lane & 15;
    const uint32_t b_base = sb + 2 * PLANE + (uint32_t)(wcol + (lb & 7)) * AS_STRIDE + (lb >> 3) * 16;

    for (int kc = 0; kc < 4; kc++) {
        const int k0 = kc * 64;
        {
            const uint4* sAh = reinterpret_cast<const uint4*>(g_xh + (size_t)arow_g * CC + k0 + chalf * 32);
            const uint4* sAl = reinterpret_cast<const uint4*>(g_xl + (size_t)arow_g * CC + k0 + chalf * 32);
            const uint4* sBh = reinterpret_cast<const uint4*>(g_Wh2 + (size_t)brow_g * CC + k0 + chalf * 32);
            const uint4* sBl = reinterpret_cast<const uint4*>(g_Wl2 + (size_t)brow_g * CC + k0 + chalf * 32);
            char* dbase = sm + (size_t)crow * AS_STRIDE + chalf * 64;
            uint4* dAh = reinterpret_cast<uint4*>(dbase);
            uint4* dAl = reinterpret_cast<uint4*>(dbase + PLANE);
            uint4* dBh = reinterpret_cast<uint4*>(dbase + 2 * PLANE);
            uint4* dBl = reinterpret_cast<uint4*>(dbase + 3 * PLANE);
#pragma unroll
            for (int q = 0; q < 4; q++) {
                dAh[q] = sAh[q];
                dAl[q] = sAl[q];
                dBh[q] = sBh[q];
                dBl[q] = sBl[q];
            }
        }
        __syncthreads();

#pragma unroll
        for (int ks = 0; ks < 4; ks++) {
            const uint32_t koff = (uint32_t)ks * 32;
            uint32_t ah[2][4], al[2][4];
#pragma unroll
            for (int mi = 0; mi < 2; mi++) {
                uint32_t ad = a_base + koff + (uint32_t)mi * 16 * AS_STRIDE;
                ldmx4(ah[mi], ad);
                ldmx4(al[mi], ad + PLANE);
            }
            uint32_t bf[8][2];
#pragma unroll
            for (int ni = 0; ni < 8; ni++)
                ldmx2(bf[ni], b_base + koff + (uint32_t)ni * 8 * AS_STRIDE);
#pragma unroll
            for (int mi = 0; mi < 2; mi++)
#pragma unroll
                for (int ni = 0; ni < 8; ni++) {
                    mma_bf16(acc[mi * 8 + ni], ah[mi], bf[ni]);
                    mma_bf16(acc[mi * 8 + ni], al[mi], bf[ni]);
                }
#pragma unroll
            for (int ni = 0; ni < 8; ni++)
                ldmx2(bf[ni], b_base + koff + (uint32_t)ni * 8 * AS_STRIDE + PLANE);
#pragma unroll
            for (int mi = 0; mi < 2; mi++)
#pragma unroll
                for (int ni = 0; ni < 8; ni++)
                    mma_bf16(acc[mi * 8 + ni], ah[mi], bf[ni]);
        }
        __syncthreads();
    }

    const int r0 = m0 + wrow + (lane >> 2);
    const int cb = n0 + wcol + (lane & 3) * 2;
#pragma unroll
    for (int ni = 0; ni < 8; ni++) {
        float2 bv = *reinterpret_cast<const float2*>(bias + cb + ni * 8);
#pragma unroll
        for (int mi = 0; mi < 2; mi++) {
            const float* a = acc[mi * 8 + ni];
            int r = r0 + mi * 16;
            if (r < M) {
                float2 o = make_float2(a[0] + bv.x, a[1] + bv.y);
                *reinterpret_cast<float2*>(g_xt + (size_t)r * CC + cb + ni * 8) = o;
            }
            if (r + 8 < M) {
                float2 o = make_float2(a[2] + bv.x, a[3] + bv.y);
                *reinterpret_cast<float2*>(g_xt + (size_t)(r + 8) * CC + cb + ni * 8) = o;
            }
        }
    }
}

// ---------------- software global barrier (hot spin, no nanosleep) ------------
__device__ __forceinline__ void gbar(int& phase) {
    __syncthreads();
    __threadfence();
    if (threadIdx.x == 0) {
        atomicAdd(&g_bar, 1);
        phase++;
        const int target = phase * MEGA_BLOCKS;
        while (*((volatile int*)&g_bar) < target) { }
    } else {
        phase++;
    }
    __syncthreads();
    __threadfence();
}

__device__ __forceinline__ int decode_stamp(int key, int round) {
    return ((key >> 17) == round) ? (IDXM - (key & IDXM)) : INF_I;
}

// ---------------- mega merge: disc/deg + build + rounds + finisher ------------
__global__ __launch_bounds__(256, 8)
void merge_mega_kernel(const int* __restrict__ ei) {
    const int tid = threadIdx.x;
    const int gt0 = blockIdx.x * blockDim.x + tid;
    const int STRIDE = MEGA_BLOCKS * 256;
    int phase = 0;

    // P0: disc0 bitmap + degree count
    for (int e = gt0; e < EE; e += STRIDE) {
        int s = ei[e];
        int t = ei[EE + e];
        atomicOr(&g_disc0[s >> 5], 1u << (s & 31));
        atomicAdd(&g_deg[t], 1);
    }
    gbar(phase);

    // P1: build initial worklist
    for (int e = gt0; e < EE; e += STRIDE) {
        int s = ei[e];
        int t = ei[EE + e];
        bool base = (s != t) && ((g_disc0[t >> 5] >> (t & 31)) & 1u);
        if (base) {
            int pos = atomicAdd(&g_cnt[0], 1);
            g_wl[0][pos] = e;
            atomicOr(&g_und[e >> 5], 1u << (e & 31));
        }
    }
    gbar(phase);

    // rounds
    for (int round = 1; round <= ROUNDS; round++) {
        const int cur = (round - 1) & 1, nxt = round & 1;
        if (gt0 == 0) g_cnt[nxt] = 0;
        const int n = g_cnt[cur];

        for (int idx = gt0; idx < n; idx += STRIDE) {
            int e = g_wl[cur][idx];
            int s = ei[e], t = ei[EE + e];
            int key = (round << 17) | (IDXM - e);
            atomicMax(&g_mUS[s], key);
            atomicMax(&g_mUT[t], key);
        }
        gbar(phase);

        for (int idx = gt0; idx < n; idx += STRIDE) {
            int e = g_wl[cur][idx];
            int s = ei[e], t = ei[EE + e];
            bool killed = (g_minFS[s] < e) || (g_minFS[t] < e) || (g_minFT[t] < e);
            bool decided;
            if (!killed) {
                int a = decode_stamp(g_mUS[s], round);
                int c = decode_stamp(g_mUS[t], round);
                int d = decode_stamp(g_mUT[t], round);
                if (a >= e && c >= e && d >= e) {
                    atomicMin(&g_minFS[s], e);
                    atomicMin(&g_minFT[t], e);
                    decided = true;
                } else {
                    int pos = atomicAdd(&g_cnt[nxt], 1);
                    g_wl[nxt][pos] = e;
                    decided = false;
                }
            } else {
                decided = true;
            }
            if (decided) atomicAnd(&g_und[e >> 5], ~(1u << (e & 31)));
        }
        gbar(phase);
    }

    // finisher: block 0, warp 0 only; everyone else exits
    if (blockIdx.x != 0 || tid >= 32) return;
    {
        __shared__ int sS[32];
        __shared__ int sT[32];
        const unsigned FULL = 0xFFFFFFFFu;
        const int lane = tid;

        for (int w0 = 0; w0 < EW_WORDS; w0 += 32) {
            int w = w0 + lane;
            unsigned word = (w < EW_WORDS) ? __ldcg(&g_und[w]) : 0u;
            unsigned nz = __ballot_sync(FULL, word != 0u);
            while (nz) {
                int j = __ffs(nz) - 1;
                nz &= nz - 1;
                unsigned ww = __shfl_sync(FULL, word, j);
                int wi = w0 + j;
                int i = wi * 32 + lane;
                bool valid = ((ww >> lane) & 1u) != 0u;
                int s = 0, t = 0;
                if (valid) { s = __ldg(&ei[i]); t = __ldg(&ei[EE + i]); }
                bool cand = false;
                if (valid) {
                    bool killed = (__ldcg(&g_minFS[s]) < i) ||
                                  (__ldcg(&g_minFS[t]) < i) ||
                                  (__ldcg(&g_minFT[t]) < i);
                    cand = !killed;
                }
                sS[lane] = s;
                sT[lane] = t;
                __syncwarp(FULL);
                unsigned candm = __ballot_sync(FULL, cand);
                if (candm) {
                    unsigned conflict = 0;
#pragma unroll
                    for (int q = 0; q < 32; q++) {
                        if (q < lane && ((candm >> q) & 1u)) {
                            int sq = sS[q], tq = sT[q];
                            if (sq == s || sq == t || tq == t) conflict |= (1u << q);
                        }
                    }
                    unsigned fired = 0;
                    unsigned decidedm = ~candm;
                    while (decidedm != FULL) {
                        bool undec = !((decidedm >> lane) & 1u);
                        bool ready = undec && ((conflict & ~decidedm) == 0u);
                        bool f = ready && ((conflict & fired) == 0u);
                        decidedm |= __ballot_sync(FULL, ready);
                        fired    |= __ballot_sync(FULL, f);
                    }
                    if ((fired >> lane) & 1u) {
                        atomicMin(&g_minFS[s], i);
                        atomicMin(&g_minFT[t], i);
                    }
                    __threadfence();
                }
                __syncwarp(FULL);
            }
        }
    }
}

// ---------------- block-scan helper -------------------------------------------
__device__ __forceinline__ int block_excl_scan(int v, int* wsums, int& total) {
    const int tid = threadIdx.x;
    const int lane = tid & 31, wid = tid >> 5;
    int p = v;
#pragma unroll
    for (int o = 1; o < 32; o <<= 1) {
        int n = __shfl_up_sync(0xFFFFFFFFu, p, o);
        if (lane >= o) p += n;
    }
    if (lane == 31) wsums[wid] = p;
    __syncthreads();
    if (wid == 0) {
        int w = (lane < 8) ? wsums[lane] : 0;
#pragma unroll
        for (int o = 1; o < 8; o <<= 1) {
            int n = __shfl_up_sync(0xFFFFFFFFu, w, o);
            if (lane >= o) w += n;
        }
        if (lane < 8) wsums[lane] = w;
    }
    __syncthreads();
    total = wsums[7];
    return p - v + (wid > 0 ? wsums[wid - 1] : 0);
}

// ---------------- scan stages ---------------------------------------------------
__global__ __launch_bounds__(256, 8)
void scan1_kernel() {
    __shared__ int wsums[8];
    int i = blockIdx.x * 256 + threadIdx.x;
    int d = 0;
    if (i < NN) {
        g_mask[i] = (g_minFS[i] == INF_I) ? 1 : 0;
        d = g_deg[i];
    }
    int lane = threadIdx.x & 31, wid = threadIdx.x >> 5;
#pragma unroll
    for (int o = 16; o > 0; o >>= 1) d += __shfl_down_sync(0xFFFFFFFFu, d, o);
    if (lane == 0) wsums[wid] = d;
    __syncthreads();
    if (threadIdx.x == 0) {
        int s = 0;
#pragma unroll
        for (int w = 0; w < 8; w++) s += wsums[w];
        g_bsum[blockIdx.x] = s;
    }
}

__global__ __launch_bounds__(256, 1)
void scan2_kernel() {
    __shared__ int wsums[8];
    const int tid = threadIdx.x;
    int v = (tid < SCAN_BLOCKS) ? g_bsum[tid] : 0;
    int total;
    int excl = block_excl_scan(v, wsums, total);
    if (tid < SCAN_BLOCKS) g_bsum[tid] = excl;
    if (tid == 0) g_off[NN] = total;
}

__global__ __launch_bounds__(256, 8)
void scan3_kernel() {
    __shared__ int wsums[8];
    int i = blockIdx.x * 256 + threadIdx.x;
    int d = (i < NN) ? g_deg[i] : 0;
    int total;
    int excl = block_excl_scan(d, wsums, total) + g_bsum[blockIdx.x];
    if (i < NN) {
        g_off[i] = excl;
        g_cur[i] = excl;
    }
}

// ---------------- CSR fill ------------------------------------------------------
__global__ void fill_kernel(const int* __restrict__ ei) {
    int e = blockIdx.x * blockDim.x + threadIdx.x;
    if (e < EE) {
        int dst = ei[EE + e];
        int p = atomicAdd(&g_cur[dst], 1);
        g_srclist[p] = ei[e];
    }
}

// ---------------- gather-mean + mask + output -----------------------------------
__global__ __launch_bounds__(256, 8)
void out_kernel(float* __restrict__ out) {
    int warp = (blockIdx.x * blockDim.x + threadIdx.x) >> 5;
    int lane = threadIdx.x & 31;
    if (warp >= NN) return;
    const int v = warp;

    float4* o = reinterpret_cast<float4*>(out + (size_t)v * CC);
    if (!g_mask[v]) {
        o[lane]      = make_float4(0.f, 0.f, 0.f, 0.f);
        o[lane + 32] = make_float4(0.f, 0.f, 0.f, 0.f);
        return;
    }
    const float4* xv = reinterpret_cast<const float4*>(g_xt + (size_t)v * CC);
    float4 a0 = xv[lane];
    float4 a1 = xv[lane + 32];
    int s0 = g_off[v], s1 = g_off[v + 1];
    for (int j = s0; j < s1; j++) {
        int u = g_srclist[j];
        const float4* p = reinterpret_cast<const float4*>(g_xt + (size_t)u * CC);
        float4 q0 = p[lane];
        float4 q1 = p[lane + 32];
        a0.x += q0.x; a0.y += q0.y; a0.z += q0.z; a0.w += q0.w;
        a1.x += q1.x; a1.y += q1.y; a1.z += q1.z; a1.w += q1.w;
    }
    float inv = 1.f / (float)(s1 - s0 + 1);
    a0.x *= inv; a0.y *= inv; a0.z *= inv; a0.w *= inv;
    a1.x *= inv; a1.y *= inv; a1.z *= inv; a1.w *= inv;
    o[lane]      = a0;
    o[lane + 32] = a1;
}

// ---------------- tail -----------------------------------------------------------
__global__ void tail_kernel(float* __restrict__ out, int out_size) {
    int i = blockIdx.x * blockDim.x + threadIdx.x;
    int idx = NN * CC + i;
    if (idx < out_size)
        out[idx] = (i < NN) ? (float)g_mask[i] : 0.f;
}

// ---------------- launch ---------------------------------------------------------
extern "C" void kernel_launch(void* const* d_in, const int* in_sizes, int n_in,
                              void* d_out, int out_size) {
    const float* x  = (const float*)d_in[0];
    const int*   ei = (const int*)d_in[1];
    const float* W  = (const float*)d_in[2];
    const float* b  = (const float*)d_in[3];
    float* out = (float*)d_out;

    const int M = in_sizes[0] / CC;   // 50000

    static int init_done = 0;
    static cudaStream_t s2;
    static cudaEvent_t evFork, evJoin;
    if (!init_done) {
        cudaFuncSetAttribute(gemm_mma_kernel, cudaFuncAttributeMaxDynamicSharedMemorySize, SMEM_GEMM);
        cudaStreamCreateWithFlags(&s2, cudaStreamNonBlocking);
        cudaEventCreateWithFlags(&evFork, cudaEventDisableTiming);
        cudaEventCreateWithFlags(&evJoin, cudaEventDisableTiming);
        init_done = 1;
    }

    // common prologue (stream 0): state init + W split
    init_prep_kernel<<<(CC * CC + 255) / 256, 256>>>(W);

    // fork: branch B (edge pipeline) onto s2
    cudaEventRecord(evFork, 0);
    cudaStreamWaitEvent(s2, evFork, 0);

    // branch A (stream 0): xsplit + GEMM
    xsplit_kernel<<<(NN * CC / 4 + 255) / 256, 256>>>(x);
    gemm_mma_kernel<<<dim3((M + 127) / 128, 2), 256, SMEM_GEMM>>>(b, M);

    // branch B (s2): fused merge + scan + CSR
    merge_mega_kernel<<<MEGA_BLOCKS, 256, 0, s2>>>(ei);
    scan1_kernel<<<SCAN_BLOCKS, 256, 0, s2>>>();
    scan2_kernel<<<1, 256, 0, s2>>>();
    scan3_kernel<<<SCAN_BLOCKS, 256, 0, s2>>>();
    fill_kernel<<<(EE + 255) / 256, 256, 0, s2>>>(ei);

    // join: stream 0 waits for branch B, then epilogue
    cudaEventRecord(evJoin, s2);
    cudaStreamWaitEvent(0, evJoin, 0);

    out_kernel<<<(NN * 32 + 255) / 256, 256>>>(out);

    int tail = out_size - NN * CC;
    if (tail > 0)
        tail_kernel<<<(tail + 255) / 256, 256>>>(out, out_size);
}

// round 14
// speedup vs baseline: 1.2475x; 1.2475x over previous
#include <cuda_runtime.h>
#include <cuda_bf16.h>
#include <cstdint>

#define NN 50000
#define EE 100000
#define CC 256
#define NW_WORDS 1568
#define INF_I 0x7FFFFFFF
#define IDXM 131071
#define ROUNDS 9
#define SCAN_BLOCKS 196
#define MEGA_BLOCKS 112
#define FCAP 2048              // finisher capacity (survivor list)
#define SMALLCAP 192           // early-exit threshold

// GEMM tiling
#define AS_STRIDE 144
#define PLANE 18432
#define SMEM_GEMM (4 * PLANE)

// ---------------- scratch (static device globals; no allocation) -------------
__device__ float g_xt[NN * CC];
__device__ __nv_bfloat16 g_xh[NN * CC];
__device__ __nv_bfloat16 g_xl[NN * CC];
__device__ __nv_bfloat16 g_Wh2[CC * CC];
__device__ __nv_bfloat16 g_Wl2[CC * CC];
__device__ int   g_deg[NN];
__device__ int   g_off[NN + 1];
__device__ int   g_cur[NN];
__device__ int   g_srclist[EE];
__device__ int   g_mask[NN];
__device__ int   g_bsum[SCAN_BLOCKS];

// merge state
__device__ int      g_minFS[NN];
__device__ int      g_minFT[NN];
__device__ int      g_mUS[2][NN];      // stamp planes by round parity
__device__ int      g_mUT[2][NN];
__device__ unsigned g_disc0[NW_WORDS];
__device__ uint2    g_wlp[2][EE];      // packed worklist: {e, s | t<<16}
__device__ int      g_cntA[4096];      // per-round counts (zeroed each call)
__device__ int      g_bar;

// ---------------- mma helpers -------------------------------------------------
__device__ __forceinline__ uint32_t smem_u32(const void* p) {
    uint32_t a;
    asm("{ .reg .u64 t; cvta.to.shared.u64 t, %1; cvt.u32.u64 %0, t; }" : "=r"(a) : "l"(p));
    return a;
}
__device__ __forceinline__ void ldmx4(uint32_t* r, uint32_t addr) {
    asm volatile("ldmatrix.sync.aligned.m8n8.x4.shared.b16 {%0,%1,%2,%3}, [%4];"
                 : "=r"(r[0]), "=r"(r[1]), "=r"(r[2]), "=r"(r[3]) : "r"(addr));
}
__device__ __forceinline__ void ldmx2(uint32_t* r, uint32_t addr) {
    asm volatile("ldmatrix.sync.aligned.m8n8.x2.shared.b16 {%0,%1}, [%2];"
                 : "=r"(r[0]), "=r"(r[1]) : "r"(addr));
}
__device__ __forceinline__ void mma_bf16(float* c, const uint32_t* a, const uint32_t* b) {
    asm volatile(
        "mma.sync.aligned.m16n8k16.row.col.f32.bf16.bf16.f32 "
        "{%0,%1,%2,%3}, {%4,%5,%6,%7}, {%8,%9}, {%0,%1,%2,%3};"
        : "+f"(c[0]), "+f"(c[1]), "+f"(c[2]), "+f"(c[3])
        : "r"(a[0]), "r"(a[1]), "r"(a[2]), "r"(a[3]), "r"(b[0]), "r"(b[1]));
}

// ---------------- fused init + W split ----------------------------------------
__global__ void init_prep_kernel(const float* __restrict__ W) {
    int i = blockIdx.x * blockDim.x + threadIdx.x;   // 65536 threads
    if (i < NN) {
        g_minFS[i] = INF_I;
        g_minFT[i] = INF_I;
        g_mUS[0][i] = 0; g_mUS[1][i] = 0;
        g_mUT[0][i] = 0; g_mUT[1][i] = 0;
        g_deg[i] = 0;
    }
    if (i < NW_WORDS) g_disc0[i] = 0u;
    if (i < 4096) g_cntA[i] = 0;
    if (i == 0) g_bar = 0;
    {
        float w = W[i];
        __nv_bfloat16 hi = __float2bfloat16_rn(w);
        __nv_bfloat16 lo = __float2bfloat16_rn(w - __bfloat162float(hi));
        g_Wh2[i] = hi;
        g_Wl2[i] = lo;
    }
}

// ---------------- x split: fp32 -> bf16 hi/lo ----------------------------------
__global__ void xsplit_kernel(const float* __restrict__ x) {
    int i = blockIdx.x * blockDim.x + threadIdx.x;
    if (i >= NN * CC / 4) return;
    float4 v = reinterpret_cast<const float4*>(x)[i];
    float f[4] = {v.x, v.y, v.z, v.w};
    __nv_bfloat16 h[4], l[4];
#pragma unroll
    for (int q = 0; q < 4; q++) {
        h[q] = __float2bfloat16_rn(f[q]);
        l[q] = __float2bfloat16_rn(f[q] - __bfloat162float(h[q]));
    }
    reinterpret_cast<uint2*>(g_xh)[i] = *reinterpret_cast<uint2*>(h);
    reinterpret_cast<uint2*>(g_xl)[i] = *reinterpret_cast<uint2*>(l);
}

// ---------------- GEMM: xt = x @ W^T + b  (mma.sync bf16 split, 3 passes) -----
__global__ __launch_bounds__(256, 2)
void gemm_mma_kernel(const float* __restrict__ bias, int M) {
    extern __shared__ char sm[];
    const uint32_t sb = smem_u32(sm);
    const int tid = threadIdx.x;
    const int warp = tid >> 5;
    const int lane = tid & 31;
    const int m0 = blockIdx.x * 128;
    const int n0 = blockIdx.y * 128;
    const int wrow = (warp & 3) * 32;
    const int wcol = (warp >> 2) * 64;

    float acc[16][4];
#pragma unroll
    for (int t = 0; t < 16; t++)
#pragma unroll
        for (int q = 0; q < 4; q++) acc[t][q] = 0.f;

    const int crow = tid >> 1;
    const int chalf = tid & 1;
    int arow_g = m0 + crow;
    if (arow_g >= M) arow_g = M - 1;
    const int brow_g = n0 + crow;

    const uint32_t a_base = sb + (uint32_t)(wrow + (lane & 15)) * AS_STRIDE + (lane >> 4) * 16;
    const int lb = lane & 15;
    const uint32_t b_base = sb + 2 * PLANE + (uint32_t)(wcol + (lb & 7)) * AS_STRIDE + (lb >> 3) * 16;

    for (int kc = 0; kc < 4; kc++) {
        const int k0 = kc * 64;
        {
            const uint4* sAh = reinterpret_cast<const uint4*>(g_xh + (size_t)arow_g * CC + k0 + chalf * 32);
            const uint4* sAl = reinterpret_cast<const uint4*>(g_xl + (size_t)arow_g * CC + k0 + chalf * 32);
            const uint4* sBh = reinterpret_cast<const uint4*>(g_Wh2 + (size_t)brow_g * CC + k0 + chalf * 32);
            const uint4* sBl = reinterpret_cast<const uint4*>(g_Wl2 + (size_t)brow_g * CC + k0 + chalf * 32);
            char* dbase = sm + (size_t)crow * AS_STRIDE + chalf * 64;
            uint4* dAh = reinterpret_cast<uint4*>(dbase);
            uint4* dAl = reinterpret_cast<uint4*>(dbase + PLANE);
            uint4* dBh = reinterpret_cast<uint4*>(dbase + 2 * PLANE);
            uint4* dBl = reinterpret_cast<uint4*>(dbase + 3 * PLANE);
#pragma unroll
            for (int q = 0; q < 4; q++) {
                dAh[q] = sAh[q];
                dAl[q] = sAl[q];
                dBh[q] = sBh[q];
                dBl[q] = sBl[q];
            }
        }
        __syncthreads();

#pragma unroll
        for (int ks = 0; ks < 4; ks++) {
            const uint32_t koff = (uint32_t)ks * 32;
            uint32_t ah[2][4], al[2][4];
#pragma unroll
            for (int mi = 0; mi < 2; mi++) {
                uint32_t ad = a_base + koff + (uint32_t)mi * 16 * AS_STRIDE;
                ldmx4(ah[mi], ad);
                ldmx4(al[mi], ad + PLANE);
            }
            uint32_t bf[8][2];
#pragma unroll
            for (int ni = 0; ni < 8; ni++)
                ldmx2(bf[ni], b_base + koff + (uint32_t)ni * 8 * AS_STRIDE);
#pragma unroll
            for (int mi = 0; mi < 2; mi++)
#pragma unroll
                for (int ni = 0; ni < 8; ni++) {
                    mma_bf16(acc[mi * 8 + ni], ah[mi], bf[ni]);
                    mma_bf16(acc[mi * 8 + ni], al[mi], bf[ni]);
                }
#pragma unroll
            for (int ni = 0; ni < 8; ni++)
                ldmx2(bf[ni], b_base + koff + (uint32_t)ni * 8 * AS_STRIDE + PLANE);
#pragma unroll
            for (int mi = 0; mi < 2; mi++)
#pragma unroll
                for (int ni = 0; ni < 8; ni++)
                    mma_bf16(acc[mi * 8 + ni], ah[mi], bf[ni]);
        }
        __syncthreads();
    }

    const int r0 = m0 + wrow + (lane >> 2);
    const int cb = n0 + wcol + (lane & 3) * 2;
#pragma unroll
    for (int ni = 0; ni < 8; ni++) {
        float2 bv = *reinterpret_cast<const float2*>(bias + cb + ni * 8);
#pragma unroll
        for (int mi = 0; mi < 2; mi++) {
            const float* a = acc[mi * 8 + ni];
            int r = r0 + mi * 16;
            if (r < M) {
                float2 o = make_float2(a[0] + bv.x, a[1] + bv.y);
                *reinterpret_cast<float2*>(g_xt + (size_t)r * CC + cb + ni * 8) = o;
            }
            if (r + 8 < M) {
                float2 o = make_float2(a[2] + bv.x, a[3] + bv.y);
                *reinterpret_cast<float2*>(g_xt + (size_t)(r + 8) * CC + cb + ni * 8) = o;
            }
        }
    }
}

// ---------------- software global barrier (hot spin) --------------------------
__device__ __forceinline__ void gbar(int& phase) {
    __syncthreads();
    __threadfence();
    if (threadIdx.x == 0) {
        atomicAdd(&g_bar, 1);
        phase++;
        const int target = phase * MEGA_BLOCKS;
        while (*((volatile int*)&g_bar) < target) { }
    } else {
        phase++;
    }
    __syncthreads();
    __threadfence();
}

__device__ __forceinline__ int decode_stamp(int key, int round) {
    return ((key >> 17) == round) ? (IDXM - (key & IDXM)) : INF_I;
}

// ---------------- mega merge: fused stamp+decide, compact finisher ------------
__global__ __launch_bounds__(256, 2)
void merge_mega_kernel(const int* __restrict__ ei) {
    __shared__ uint32_t sEu[FCAP];
    __shared__ uint32_t sSTu[FCAP];
    __shared__ uint32_t sE[FCAP];
    __shared__ uint32_t sST[FCAP];

    const int tid = threadIdx.x;
    const int gt0 = blockIdx.x * blockDim.x + tid;
    const int STRIDE = MEGA_BLOCKS * 256;
    int phase = 0;

    // P0: disc0 bitmap + degree count
    for (int e = gt0; e < EE; e += STRIDE) {
        int s = ei[e];
        int t = ei[EE + e];
        atomicOr(&g_disc0[s >> 5], 1u << (s & 31));
        atomicAdd(&g_deg[t], 1);
    }
    gbar(phase);

    // P1: build worklist 0 + stamp round 1 (plane 1)
    for (int e = gt0; e < EE; e += STRIDE) {
        int s = ei[e];
        int t = ei[EE + e];
        bool base = (s != t) && ((g_disc0[t >> 5] >> (t & 31)) & 1u);
        if (base) {
            int pos = atomicAdd(&g_cntA[0], 1);
            g_wlp[0][pos] = make_uint2((unsigned)e, (unsigned)s | ((unsigned)t << 16));
            int key = (1 << 17) | (IDXM - e);
            atomicMax(&g_mUS[1][s], key);
            atomicMax(&g_mUT[1][t], key);
        }
    }
    gbar(phase);

    // rounds: decide(r) reads plane r&1, writes next-round stamps to plane (r+1)&1
    int round = 1;
    int lastRound;
    while (true) {
        const int cur = (round - 1) & 1, nxt = round & 1;
        const int rp = round & 1, wp = (round + 1) & 1;
        const int n = __ldcg(&g_cntA[round - 1]);
        const int nkey_base = ((round + 1) << 17);

        for (int idx = gt0; idx < n; idx += STRIDE) {
            uint2 rec = g_wlp[cur][idx];
            int e = (int)rec.x;
            int s = (int)(rec.y & 0xFFFFu);
            int t = (int)(rec.y >> 16);

            bool killed = (g_minFS[s] < e) || (g_minFS[t] < e) || (g_minFT[t] < e);
            if (!killed) {
                int a = decode_stamp(g_mUS[rp][s], round);
                int c = decode_stamp(g_mUS[rp][t], round);
                int d = decode_stamp(g_mUT[rp][t], round);
                if (a >= e && c >= e && d >= e) {
                    atomicMin(&g_minFS[s], e);
                    atomicMin(&g_minFT[t], e);
                } else {
                    int pos = atomicAdd(&g_cntA[round], 1);
                    g_wlp[nxt][pos] = rec;
                    int key = nkey_base | (IDXM - e);
                    atomicMax(&g_mUS[wp][s], key);
                    atomicMax(&g_mUT[wp][t], key);
                }
            }
        }
        gbar(phase);

        int n2 = __ldcg(&g_cntA[round]);
        lastRound = round;
        if (n2 == 0 || n2 <= SMALLCAP ||
            (round >= ROUNDS && n2 <= FCAP) || round >= 4000) break;
        round++;
    }

    // finisher: block 0 sorts survivor list, then warp 0 runs exact greedy
    if (blockIdx.x != 0) return;
    const int n = __ldcg(&g_cntA[lastRound]);
    if (n > 0 && n <= FCAP) {
        const uint2* list = g_wlp[lastRound & 1];
        for (int i = tid; i < n; i += 256) {
            uint2 v = __ldcg(&((const uint2*)list)[i]);
            sEu[i] = v.x;
            sSTu[i] = v.y;
        }
        __syncthreads();
        // rank sort by edge index (all distinct)
        for (int i = tid; i < n; i += 256) {
            uint32_t e = sEu[i];
            int rank = 0;
            for (int j = 0; j < n; j++) rank += (sEu[j] < e);
            sE[rank] = e;
            sST[rank] = sSTu[i];
        }
        __syncthreads();

        if (tid < 32) {
            const unsigned FULL = 0xFFFFFFFFu;
            const int lane = tid;
            for (int w0 = 0; w0 < n; w0 += 32) {
                int ii = w0 + lane;
                bool valid = (ii < n);
                int e = 0, s = -1, t = -2;
                if (valid) {
                    e = (int)sE[ii];
                    uint32_t st = sST[ii];
                    s = (int)(st & 0xFFFFu);
                    t = (int)(st >> 16);
                }
                bool cand = false;
                if (valid) {
                    bool killed = (__ldcg(&g_minFS[s]) < e) ||
                                  (__ldcg(&g_minFS[t]) < e) ||
                                  (__ldcg(&g_minFT[t]) < e);
                    cand = !killed;
                }
                unsigned candm = __ballot_sync(FULL, cand);
                if (candm) {
                    unsigned conflict = 0;
#pragma unroll
                    for (int q = 0; q < 32; q++) {
                        int sq = __shfl_sync(FULL, s, q);
                        int tq = __shfl_sync(FULL, t, q);
                        if (q < lane && ((candm >> q) & 1u)) {
                            if (sq == s || sq == t || tq == t) conflict |= (1u << q);
                        }
                    }
                    unsigned fired = 0;
                    unsigned decidedm = ~candm;
                    while (decidedm != FULL) {
                        bool undec = !((decidedm >> lane) & 1u);
                        bool ready = undec && ((conflict & ~decidedm) == 0u);
                        bool f = ready && ((conflict & fired) == 0u);
                        decidedm |= __ballot_sync(FULL, ready);
                        fired    |= __ballot_sync(FULL, f);
                    }
                    if ((fired >> lane) & 1u) {
                        atomicMin(&g_minFS[s], e);
                        atomicMin(&g_minFT[t], e);
                    }
                    __threadfence();
                }
                __syncwarp(FULL);
            }
        }
    }
}

// ---------------- block-scan helper -------------------------------------------
__device__ __forceinline__ int block_excl_scan(int v, int* wsums, int& total) {
    const int tid = threadIdx.x;
    const int lane = tid & 31, wid = tid >> 5;
    int p = v;
#pragma unroll
    for (int o = 1; o < 32; o <<= 1) {
        int n = __shfl_up_sync(0xFFFFFFFFu, p, o);
        if (lane >= o) p += n;
    }
    if (lane == 31) wsums[wid] = p;
    __syncthreads();
    if (wid == 0) {
        int w = (lane < 8) ? wsums[lane] : 0;
#pragma unroll
        for (int o = 1; o < 8; o <<= 1) {
            int n = __shfl_up_sync(0xFFFFFFFFu, w, o);
            if (lane >= o) w += n;
        }
        if (lane < 8) wsums[lane] = w;
    }
    __syncthreads();
    total = wsums[7];
    return p - v + (wid > 0 ? wsums[wid - 1] : 0);
}

// ---------------- scan stages ---------------------------------------------------
__global__ __launch_bounds__(256, 8)
void scan1_kernel() {
    __shared__ int wsums[8];
    int i = blockIdx.x * 256 + threadIdx.x;
    int d = 0;
    if (i < NN) {
        g_mask[i] = (g_minFS[i] == INF_I) ? 1 : 0;
        d = g_deg[i];
    }
    int lane = threadIdx.x & 31, wid = threadIdx.x >> 5;
#pragma unroll
    for (int o = 16; o > 0; o >>= 1) d += __shfl_down_sync(0xFFFFFFFFu, d, o);
    if (lane == 0) wsums[wid] = d;
    __syncthreads();
    if (threadIdx.x == 0) {
        int s = 0;
#pragma unroll
        for (int w = 0; w < 8; w++) s += wsums[w];
        g_bsum[blockIdx.x] = s;
    }
}

__global__ __launch_bounds__(256, 1)
void scan2_kernel() {
    __shared__ int wsums[8];
    const int tid = threadIdx.x;
    int v = (tid < SCAN_BLOCKS) ? g_bsum[tid] : 0;
    int total;
    int excl = block_excl_scan(v, wsums, total);
    if (tid < SCAN_BLOCKS) g_bsum[tid] = excl;
    if (tid == 0) g_off[NN] = total;
}

__global__ __launch_bounds__(256, 8)
void scan3_kernel() {
    __shared__ int wsums[8];
    int i = blockIdx.x * 256 + threadIdx.x;
    int d = (i < NN) ? g_deg[i] : 0;
    int total;
    int excl = block_excl_scan(d, wsums, total) + g_bsum[blockIdx.x];
    if (i < NN) {
        g_off[i] = excl;
        g_cur[i] = excl;
    }
}

// ---------------- CSR fill ------------------------------------------------------
__global__ void fill_kernel(const int* __restrict__ ei) {
    int e = blockIdx.x * blockDim.x + threadIdx.x;
    if (e < EE) {
        int dst = ei[EE + e];
        int p = atomicAdd(&g_cur[dst], 1);
        g_srclist[p] = ei[e];
    }
}

// ---------------- gather-mean + mask + output -----------------------------------
__global__ __launch_bounds__(256, 8)
void out_kernel(float* __restrict__ out) {
    int warp = (blockIdx.x * blockDim.x + threadIdx.x) >> 5;
    int lane = threadIdx.x & 31;
    if (warp >= NN) return;
    const int v = warp;

    float4* o = reinterpret_cast<float4*>(out + (size_t)v * CC);
    if (!g_mask[v]) {
        o[lane]      = make_float4(0.f, 0.f, 0.f, 0.f);
        o[lane + 32] = make_float4(0.f, 0.f, 0.f, 0.f);
        return;
    }
    const float4* xv = reinterpret_cast<const float4*>(g_xt + (size_t)v * CC);
    float4 a0 = xv[lane];
    float4 a1 = xv[lane + 32];
    int s0 = g_off[v], s1 = g_off[v + 1];
    for (int j = s0; j < s1; j++) {
        int u = g_srclist[j];
        const float4* p = reinterpret_cast<const float4*>(g_xt + (size_t)u * CC);
        float4 q0 = p[lane];
        float4 q1 = p[lane + 32];
        a0.x += q0.x; a0.y += q0.y; a0.z += q0.z; a0.w += q0.w;
        a1.x += q1.x; a1.y += q1.y; a1.z += q1.z; a1.w += q1.w;
    }
    float inv = 1.f / (float)(s1 - s0 + 1);
    a0.x *= inv; a0.y *= inv; a0.z *= inv; a0.w *= inv;
    a1.x *= inv; a1.y *= inv; a1.z *= inv; a1.w *= inv;
    o[lane]      = a0;
    o[lane + 32] = a1;
}

// ---------------- tail -----------------------------------------------------------
__global__ void tail_kernel(float* __restrict__ out, int out_size) {
    int i = blockIdx.x * blockDim.x + threadIdx.x;
    int idx = NN * CC + i;
    if (idx < out_size)
        out[idx] = (i < NN) ? (float)g_mask[i] : 0.f;
}

// ---------------- launch ---------------------------------------------------------
extern "C" void kernel_launch(void* const* d_in, const int* in_sizes, int n_in,
                              void* d_out, int out_size) {
    const float* x  = (const float*)d_in[0];
    const int*   ei = (const int*)d_in[1];
    const float* W  = (const float*)d_in[2];
    const float* b  = (const float*)d_in[3];
    float* out = (float*)d_out;

    const int M = in_sizes[0] / CC;   // 50000

    static int init_done = 0;
    static cudaStream_t s2;
    static cudaEvent_t evFork, evJoin;
    if (!init_done) {
        cudaFuncSetAttribute(gemm_mma_kernel, cudaFuncAttributeMaxDynamicSharedMemorySize, SMEM_GEMM);
        cudaStreamCreateWithFlags(&s2, cudaStreamNonBlocking);
        cudaEventCreateWithFlags(&evFork, cudaEventDisableTiming);
        cudaEventCreateWithFlags(&evJoin, cudaEventDisableTiming);
        init_done = 1;
    }

    // common prologue (stream 0): state init + W split
    init_prep_kernel<<<(CC * CC + 255) / 256, 256>>>(W);

    // fork: branch B (edge pipeline) onto s2
    cudaEventRecord(evFork, 0);
    cudaStreamWaitEvent(s2, evFork, 0);

    // branch A (stream 0): xsplit + GEMM
    xsplit_kernel<<<(NN * CC / 4 + 255) / 256, 256>>>(x);
    gemm_mma_kernel<<<dim3((M + 127) / 128, 2), 256, SMEM_GEMM>>>(b, M);

    // branch B (s2): fused merge + scan + CSR
    merge_mega_kernel<<<MEGA_BLOCKS, 256, 0, s2>>>(ei);
    scan1_kernel<<<SCAN_BLOCKS, 256, 0, s2>>>();
    scan2_kernel<<<1, 256, 0, s2>>>();
    scan3_kernel<<<SCAN_BLOCKS, 256, 0, s2>>>();
    fill_kernel<<<(EE + 255) / 256, 256, 0, s2>>>(ei);

    // join: stream 0 waits for branch B, then epilogue
    cudaEventRecord(evJoin, s2);
    cudaStreamWaitEvent(0, evJoin, 0);

    out_kernel<<<(NN * 32 + 255) / 256, 256>>>(out);

    int tail = out_size - NN * CC;
    if (tail > 0)
        tail_kernel<<<(tail + 255) / 256, 256>>>(out, out_size);
}

// round 16
// speedup vs baseline: 1.2643x; 1.0135x over previous
#include <cuda_runtime.h>
#include <cuda_bf16.h>
#include <cstdint>

#define NN 50000
#define EE 100000
#define CC 256
#define NW_WORDS 1568
#define INF_I 0x7FFFFFFF
#define IDXM 131071
#define ROUNDS 9
#define SCAN_BLOCKS 196
#define MEGA_BLOCKS 112
#define FCAP 2048
#define SMALLCAP 192

// GEMM tiling
#define AS_STRIDE 144
#define PLANE 18432
#define SMEM_GEMM (4 * PLANE)

// ---------------- scratch (static device globals; no allocation) -------------
__device__ float g_xt[NN * CC];
__device__ __nv_bfloat16 g_xh[NN * CC];
__device__ __nv_bfloat16 g_xl[NN * CC];
__device__ __nv_bfloat16 g_Wh2[CC * CC];
__device__ __nv_bfloat16 g_Wl2[CC * CC];
__device__ int   g_deg[NN];
__device__ int   g_off[NN + 1];
__device__ int   g_cur[NN];
__device__ int   g_srclist[EE];
__device__ int   g_mask[NN];
__device__ int   g_bsum[SCAN_BLOCKS];

// merge state
__device__ int      g_minFS[NN];
__device__ int      g_minFT[NN];
__device__ int      g_mUS[2][NN];
__device__ int      g_mUT[2][NN];
__device__ unsigned g_disc0[NW_WORDS];
__device__ uint2    g_wlp[2][EE];
__device__ int      g_cntA[4096];
__device__ int      g_bar;

// ---------------- mma helpers -------------------------------------------------
__device__ __forceinline__ uint32_t smem_u32(const void* p) {
    uint32_t a;
    asm("{ .reg .u64 t; cvta.to.shared.u64 t, %1; cvt.u32.u64 %0, t; }" : "=r"(a) : "l"(p));
    return a;
}
__device__ __forceinline__ void ldmx4(uint32_t* r, uint32_t addr) {
    asm volatile("ldmatrix.sync.aligned.m8n8.x4.shared.b16 {%0,%1,%2,%3}, [%4];"
                 : "=r"(r[0]), "=r"(r[1]), "=r"(r[2]), "=r"(r[3]) : "r"(addr));
}
__device__ __forceinline__ void mma_bf16(float* c, const uint32_t* a, const uint32_t* b) {
    asm volatile(
        "mma.sync.aligned.m16n8k16.row.col.f32.bf16.bf16.f32 "
        "{%0,%1,%2,%3}, {%4,%5,%6,%7}, {%8,%9}, {%0,%1,%2,%3};"
        : "+f"(c[0]), "+f"(c[1]), "+f"(c[2]), "+f"(c[3])
        : "r"(a[0]), "r"(a[1]), "r"(a[2]), "r"(a[3]), "r"(b[0]), "r"(b[1]));
}

// ---------------- fused init + W split ----------------------------------------
__global__ void init_prep_kernel(const float* __restrict__ W) {
    int i = blockIdx.x * blockDim.x + threadIdx.x;   // 65536 threads
    if (i < NN) {
        g_minFS[i] = INF_I;
        g_minFT[i] = INF_I;
        g_mUS[0][i] = 0; g_mUS[1][i] = 0;
        g_mUT[0][i] = 0; g_mUT[1][i] = 0;
        g_deg[i] = 0;
    }
    if (i < NW_WORDS) g_disc0[i] = 0u;
    if (i < 4096) g_cntA[i] = 0;
    if (i == 0) g_bar = 0;
    {
        float w = W[i];
        __nv_bfloat16 hi = __float2bfloat16_rn(w);
        __nv_bfloat16 lo = __float2bfloat16_rn(w - __bfloat162float(hi));
        g_Wh2[i] = hi;
        g_Wl2[i] = lo;
    }
}

// ---------------- x split: fp32 -> bf16 hi/lo ----------------------------------
__global__ void xsplit_kernel(const float* __restrict__ x) {
    int i = blockIdx.x * blockDim.x + threadIdx.x;
    if (i >= NN * CC / 4) return;
    float4 v = reinterpret_cast<const float4*>(x)[i];
    float f[4] = {v.x, v.y, v.z, v.w};
    __nv_bfloat16 h[4], l[4];
#pragma unroll
    for (int q = 0; q < 4; q++) {
        h[q] = __float2bfloat16_rn(f[q]);
        l[q] = __float2bfloat16_rn(f[q] - __bfloat162float(h[q]));
    }
    reinterpret_cast<uint2*>(g_xh)[i] = *reinterpret_cast<uint2*>(h);
    reinterpret_cast<uint2*>(g_xl)[i] = *reinterpret_cast<uint2*>(l);
}

// ---------------- GEMM: xt = x @ W^T + b  (mma.sync bf16 split, 3 passes) -----
__global__ __launch_bounds__(256, 2)
void gemm_mma_kernel(const float* __restrict__ bias, int M) {
    extern __shared__ char sm[];
    const uint32_t sb = smem_u32(sm);
    const int tid = threadIdx.x;
    const int warp = tid >> 5;
    const int lane = tid & 31;
    const int m0 = blockIdx.x * 128;
    const int n0 = blockIdx.y * 128;
    const int wrow = (warp & 3) * 32;
    const int wcol = (warp >> 2) * 64;

    float acc[16][4];
#pragma unroll
    for (int t = 0; t < 16; t++)
#pragma unroll
        for (int q = 0; q < 4; q++) acc[t][q] = 0.f;

    const int crow = tid >> 1;
    const int chalf = tid & 1;
    int arow_g = m0 + crow;
    if (arow_g >= M) arow_g = M - 1;
    const int brow_g = n0 + crow;

    const uint32_t a_base = sb + (uint32_t)(wrow + (lane & 15)) * AS_STRIDE + (lane >> 4) * 16;
    // B x4 pairing: lanes 0-7 -> tile ni k0-7, 8-15 -> ni k8-15,
    //               lanes 16-23 -> ni+1 k0-7, 24-31 -> ni+1 k8-15
    const uint32_t b_base = sb + 2 * PLANE
        + (uint32_t)(wcol + ((lane >> 4) * 8) + (lane & 7)) * AS_STRIDE
        + (((lane >> 3) & 1) * 16);

    for (int kc = 0; kc < 4; kc++) {
        const int k0 = kc * 64;
        {
            const uint4* sAh = reinterpret_cast<const uint4*>(g_xh + (size_t)arow_g * CC + k0 + chalf * 32);
            const uint4* sAl = reinterpret_cast<const uint4*>(g_xl + (size_t)arow_g * CC + k0 + chalf * 32);
            const uint4* sBh = reinterpret_cast<const uint4*>(g_Wh2 + (size_t)brow_g * CC + k0 + chalf * 32);
            const uint4* sBl = reinterpret_cast<const uint4*>(g_Wl2 + (size_t)brow_g * CC + k0 + chalf * 32);
            char* dbase = sm + (size_t)crow * AS_STRIDE + chalf * 64;
            uint4* dAh = reinterpret_cast<uint4*>(dbase);
            uint4* dAl = reinterpret_cast<uint4*>(dbase + PLANE);
            uint4* dBh = reinterpret_cast<uint4*>(dbase + 2 * PLANE);
            uint4* dBl = reinterpret_cast<uint4*>(dbase + 3 * PLANE);
#pragma unroll
            for (int q = 0; q < 4; q++) {
                dAh[q] = sAh[q];
                dAl[q] = sAl[q];
                dBh[q] = sBh[q];
                dBl[q] = sBl[q];
            }
        }
        __syncthreads();

#pragma unroll
        for (int ks = 0; ks < 4; ks++) {
            const uint32_t koff = (uint32_t)ks * 32;
            uint32_t ah[2][4], al[2][4];
#pragma unroll
            for (int mi = 0; mi < 2; mi++) {
                uint32_t ad = a_base + koff + (uint32_t)mi * 16 * AS_STRIDE;
                ldmx4(ah[mi], ad);
                ldmx4(al[mi], ad + PLANE);
            }
            uint32_t bf[8][2];
            // B hi: 4 x4-loads cover 8 n8-tiles
#pragma unroll
            for (int np = 0; np < 4; np++) {
                uint32_t r4[4];
                ldmx4(r4, b_base + koff + (uint32_t)np * 16 * AS_STRIDE);
                bf[2 * np][0] = r4[0]; bf[2 * np][1] = r4[1];
                bf[2 * np + 1][0] = r4[2]; bf[2 * np + 1][1] = r4[3];
            }
#pragma unroll
            for (int mi = 0; mi < 2; mi++)
#pragma unroll
                for (int ni = 0; ni < 8; ni++) {
                    mma_bf16(acc[mi * 8 + ni], ah[mi], bf[ni]);
                    mma_bf16(acc[mi * 8 + ni], al[mi], bf[ni]);
                }
            // B lo
#pragma unroll
            for (int np = 0; np < 4; np++) {
                uint32_t r4[4];
                ldmx4(r4, b_base + koff + (uint32_t)np * 16 * AS_STRIDE + PLANE);
                bf[2 * np][0] = r4[0]; bf[2 * np][1] = r4[1];
                bf[2 * np + 1][0] = r4[2]; bf[2 * np + 1][1] = r4[3];
            }
#pragma unroll
            for (int mi = 0; mi < 2; mi++)
#pragma unroll
                for (int ni = 0; ni < 8; ni++)
                    mma_bf16(acc[mi * 8 + ni], ah[mi], bf[ni]);
        }
        __syncthreads();
    }

    const int r0 = m0 + wrow + (lane >> 2);
    const int cb = n0 + wcol + (lane & 3) * 2;
#pragma unroll
    for (int ni = 0; ni < 8; ni++) {
        float2 bv = *reinterpret_cast<const float2*>(bias + cb + ni * 8);
#pragma unroll
        for (int mi = 0; mi < 2; mi++) {
            const float* a = acc[mi * 8 + ni];
            int r = r0 + mi * 16;
            if (r < M) {
                float2 o = make_float2(a[0] + bv.x, a[1] + bv.y);
                *reinterpret_cast<float2*>(g_xt + (size_t)r * CC + cb + ni * 8) = o;
            }
            if (r + 8 < M) {
                float2 o = make_float2(a[2] + bv.x, a[3] + bv.y);
                *reinterpret_cast<float2*>(g_xt + (size_t)(r + 8) * CC + cb + ni * 8) = o;
            }
        }
    }
}

// ---------------- software global barrier (hot spin) --------------------------
__device__ __forceinline__ void gbar(int& phase) {
    __syncthreads();
    __threadfence();
    if (threadIdx.x == 0) {
        atomicAdd(&g_bar, 1);
        phase++;
        const int target = phase * MEGA_BLOCKS;
        while (*((volatile int*)&g_bar) < target) { }
    } else {
        phase++;
    }
    __syncthreads();
    __threadfence();
}

__device__ __forceinline__ int decode_stamp(int key, int round) {
    return ((key >> 17) == round) ? (IDXM - (key & IDXM)) : INF_I;
}

// ---------------- mega merge: fused stamp+decide, compact finisher ------------
__global__ __launch_bounds__(256, 2)
void merge_mega_kernel(const int* __restrict__ ei) {
    __shared__ uint32_t sEu[FCAP];
    __shared__ uint32_t sSTu[FCAP];
    __shared__ uint32_t sE[FCAP];
    __shared__ uint32_t sST[FCAP];

    const int tid = threadIdx.x;
    const int gt0 = blockIdx.x * blockDim.x + tid;
    const int STRIDE = MEGA_BLOCKS * 256;
    int phase = 0;

    // P0: disc0 bitmap + degree count
    for (int e = gt0; e < EE; e += STRIDE) {
        int s = ei[e];
        int t = ei[EE + e];
        atomicOr(&g_disc0[s >> 5], 1u << (s & 31));
        atomicAdd(&g_deg[t], 1);
    }
    gbar(phase);

    // P1: build worklist 0 + stamp round 1 (plane 1)
    for (int e = gt0; e < EE; e += STRIDE) {
        int s = ei[e];
        int t = ei[EE + e];
        bool base = (s != t) && ((g_disc0[t >> 5] >> (t & 31)) & 1u);
        if (base) {
            int pos = atomicAdd(&g_cntA[0], 1);
            g_wlp[0][pos] = make_uint2((unsigned)e, (unsigned)s | ((unsigned)t << 16));
            int key = (1 << 17) | (IDXM - e);
            atomicMax(&g_mUS[1][s], key);
            atomicMax(&g_mUT[1][t], key);
        }
    }
    gbar(phase);

    // rounds: decide(r) reads plane r&1, writes next-round stamps to plane (r+1)&1
    int round = 1;
    int lastRound;
    while (true) {
        const int cur = (round - 1) & 1, nxt = round & 1;
        const int rp = round & 1, wp = (round + 1) & 1;
        const int n = __ldcg(&g_cntA[round - 1]);
        const int nkey_base = ((round + 1) << 17);

        for (int idx = gt0; idx < n; idx += STRIDE) {
            uint2 rec = g_wlp[cur][idx];
            int e = (int)rec.x;
            int s = (int)(rec.y & 0xFFFFu);
            int t = (int)(rec.y >> 16);

            bool killed = (g_minFS[s] < e) || (g_minFS[t] < e) || (g_minFT[t] < e);
            if (!killed) {
                int a = decode_stamp(g_mUS[rp][s], round);
                int c = decode_stamp(g_mUS[rp][t], round);
                int d = decode_stamp(g_mUT[rp][t], round);
                if (a >= e && c >= e && d >= e) {
                    atomicMin(&g_minFS[s], e);
                    atomicMin(&g_minFT[t], e);
                } else {
                    int pos = atomicAdd(&g_cntA[round], 1);
                    g_wlp[nxt][pos] = rec;
                    int key = nkey_base | (IDXM - e);
                    atomicMax(&g_mUS[wp][s], key);
                    atomicMax(&g_mUT[wp][t], key);
                }
            }
        }
        gbar(phase);

        int n2 = __ldcg(&g_cntA[round]);
        lastRound = round;
        if (n2 == 0 || n2 <= SMALLCAP ||
            (round >= ROUNDS && n2 <= FCAP) || round >= 4000) break;
        round++;
    }

    // finisher: block 0 sorts survivor list, then warp 0 runs exact greedy
    if (blockIdx.x != 0) return;
    const int n = __ldcg(&g_cntA[lastRound]);
    if (n > 0 && n <= FCAP) {
        const uint2* list = g_wlp[lastRound & 1];
        for (int i = tid; i < n; i += 256) {
            uint2 v = __ldcg(&((const uint2*)list)[i]);
            sEu[i] = v.x;
            sSTu[i] = v.y;
        }
        __syncthreads();
        for (int i = tid; i < n; i += 256) {
            uint32_t e = sEu[i];
            int rank = 0;
            for (int j = 0; j < n; j++) rank += (sEu[j] < e);
            sE[rank] = e;
            sST[rank] = sSTu[i];
        }
        __syncthreads();

        if (tid < 32) {
            const unsigned FULL = 0xFFFFFFFFu;
            const int lane = tid;
            for (int w0 = 0; w0 < n; w0 += 32) {
                int ii = w0 + lane;
                bool valid = (ii < n);
                int e = 0, s = -1, t = -2;
                if (valid) {
                    e = (int)sE[ii];
                    uint32_t st = sST[ii];
                    s = (int)(st & 0xFFFFu);
                    t = (int)(st >> 16);
                }
                bool cand = false;
                if (valid) {
                    bool killed = (__ldcg(&g_minFS[s]) < e) ||
                                  (__ldcg(&g_minFS[t]) < e) ||
                                  (__ldcg(&g_minFT[t]) < e);
                    cand = !killed;
                }
                unsigned candm = __ballot_sync(FULL, cand);
                if (candm) {
                    unsigned conflict = 0;
#pragma unroll
                    for (int q = 0; q < 32; q++) {
                        int sq = __shfl_sync(FULL, s, q);
                        int tq = __shfl_sync(FULL, t, q);
                        if (q < lane && ((candm >> q) & 1u)) {
                            if (sq == s || sq == t || tq == t) conflict |= (1u << q);
                        }
                    }
                    unsigned fired = 0;
                    unsigned decidedm = ~candm;
                    while (decidedm != FULL) {
                        bool undec = !((decidedm >> lane) & 1u);
                        bool ready = undec && ((conflict & ~decidedm) == 0u);
                        bool f = ready && ((conflict & fired) == 0u);
                        decidedm |= __ballot_sync(FULL, ready);
                        fired    |= __ballot_sync(FULL, f);
                    }
                    if ((fired >> lane) & 1u) {
                        atomicMin(&g_minFS[s], e);
                        atomicMin(&g_minFT[t], e);
                    }
                    __threadfence();
                }
                __syncwarp(FULL);
            }
        }
    }
}

// ---------------- block-scan helper -------------------------------------------
__device__ __forceinline__ int block_excl_scan(int v, int* wsums, int& total) {
    const int tid = threadIdx.x;
    const int lane = tid & 31, wid = tid >> 5;
    int p = v;
#pragma unroll
    for (int o = 1; o < 32; o <<= 1) {
        int n = __shfl_up_sync(0xFFFFFFFFu, p, o);
        if (lane >= o) p += n;
    }
    if (lane == 31) wsums[wid] = p;
    __syncthreads();
    if (wid == 0) {
        int w = (lane < 8) ? wsums[lane] : 0;
#pragma unroll
        for (int o = 1; o < 8; o <<= 1) {
            int n = __shfl_up_sync(0xFFFFFFFFu, w, o);
            if (lane >= o) w += n;
        }
        if (lane < 8) wsums[lane] = w;
    }
    __syncthreads();
    total = wsums[7];
    return p - v + (wid > 0 ? wsums[wid - 1] : 0);
}

// ---------------- scan stages ---------------------------------------------------
__global__ __launch_bounds__(256, 8)
void scan1_kernel() {
    __shared__ int wsums[8];
    int i = blockIdx.x * 256 + threadIdx.x;
    int d = 0;
    if (i < NN) {
        g_mask[i] = (g_minFS[i] == INF_I) ? 1 : 0;
        d = g_deg[i];
    }
    int lane = threadIdx.x & 31, wid = threadIdx.x >> 5;
#pragma unroll
    for (int o = 16; o > 0; o >>= 1) d += __shfl_down_sync(0xFFFFFFFFu, d, o);
    if (lane == 0) wsums[wid] = d;
    __syncthreads();
    if (threadIdx.x == 0) {
        int s = 0;
#pragma unroll
        for (int w = 0; w < 8; w++) s += wsums[w];
        g_bsum[blockIdx.x] = s;
    }
}

__global__ __launch_bounds__(256, 1)
void scan2_kernel() {
    __shared__ int wsums[8];
    const int tid = threadIdx.x;
    int v = (tid < SCAN_BLOCKS) ? g_bsum[tid] : 0;
    int total;
    int excl = block_excl_scan(v, wsums, total);
    if (tid < SCAN_BLOCKS) g_bsum[tid] = excl;
    if (tid == 0) g_off[NN] = total;
}

__global__ __launch_bounds__(256, 8)
void scan3_kernel() {
    __shared__ int wsums[8];
    int i = blockIdx.x * 256 + threadIdx.x;
    int d = (i < NN) ? g_deg[i] : 0;
    int total;
    int excl = block_excl_scan(d, wsums, total) + g_bsum[blockIdx.x];
    if (i < NN) {
        g_off[i] = excl;
        g_cur[i] = excl;
    }
}

// ---------------- CSR fill ------------------------------------------------------
__global__ void fill_kernel(const int* __restrict__ ei) {
    int e = blockIdx.x * blockDim.x + threadIdx.x;
    if (e < EE) {
        int dst = ei[EE + e];
        int p = atomicAdd(&g_cur[dst], 1);
        g_srclist[p] = ei[e];
    }
}

// ---------------- gather-mean + mask + output -----------------------------------
__global__ __launch_bounds__(256, 8)
void out_kernel(float* __restrict__ out) {
    int warp = (blockIdx.x * blockDim.x + threadIdx.x) >> 5;
    int lane = threadIdx.x & 31;
    if (warp >= NN) return;
    const int v = warp;

    float4* o = reinterpret_cast<float4*>(out + (size_t)v * CC);
    if (!g_mask[v]) {
        o[lane]      = make_float4(0.f, 0.f, 0.f, 0.f);
        o[lane + 32] = make_float4(0.f, 0.f, 0.f, 0.f);
        return;
    }
    const float4* xv = reinterpret_cast<const float4*>(g_xt + (size_t)v * CC);
    float4 a0 = xv[lane];
    float4 a1 = xv[lane + 32];
    int s0 = g_off[v], s1 = g_off[v + 1];
    for (int j = s0; j < s1; j++) {
        int u = g_srclist[j];
        const float4* p = reinterpret_cast<const float4*>(g_xt + (size_t)u * CC);
        float4 q0 = p[lane];
        float4 q1 = p[lane + 32];
        a0.x += q0.x; a0.y += q0.y; a0.z += q0.z; a0.w += q0.w;
        a1.x += q1.x; a1.y += q1.y; a1.z += q1.z; a1.w += q1.w;
    }
    float inv = 1.f / (float)(s1 - s0 + 1);
    a0.x *= inv; a0.y *= inv; a0.z *= inv; a0.w *= inv;
    a1.x *= inv; a1.y *= inv; a1.z *= inv; a1.w *= inv;
    o[lane]      = a0;
    o[lane + 32] = a1;
}

// ---------------- tail -----------------------------------------------------------
__global__ void tail_kernel(float* __restrict__ out, int out_size) {
    int i = blockIdx.x * blockDim.x + threadIdx.x;
    int idx = NN * CC + i;
    if (idx < out_size)
        out[idx] = (i < NN) ? (float)g_mask[i] : 0.f;
}

// ---------------- launch ---------------------------------------------------------
extern "C" void kernel_launch(void* const* d_in, const int* in_sizes, int n_in,
                              void* d_out, int out_size) {
    const float* x  = (const float*)d_in[0];
    const int*   ei = (const int*)d_in[1];
    const float* W  = (const float*)d_in[2];
    const float* b  = (const float*)d_in[3];
    float* out = (float*)d_out;

    const int M = in_sizes[0] / CC;   // 50000

    static int init_done = 0;
    static cudaStream_t s2;
    static cudaEvent_t evFork, evJoin;
    if (!init_done) {
        cudaFuncSetAttribute(gemm_mma_kernel, cudaFuncAttributeMaxDynamicSharedMemorySize, SMEM_GEMM);
        cudaStreamCreateWithFlags(&s2, cudaStreamNonBlocking);
        cudaEventCreateWithFlags(&evFork, cudaEventDisableTiming);
        cudaEventCreateWithFlags(&evJoin, cudaEventDisableTiming);
        init_done = 1;
    }

    // common prologue (stream 0): state init + W split
    init_prep_kernel<<<(CC * CC + 255) / 256, 256>>>(W);

    // fork: branch B (edge pipeline) onto s2 (legal capture fork: record on origin, wait on s2)
    cudaEventRecord(evFork, 0);
    cudaStreamWaitEvent(s2, evFork, 0);

    // branch A (stream 0): xsplit + GEMM
    xsplit_kernel<<<(NN * CC / 4 + 255) / 256, 256>>>(x);
    gemm_mma_kernel<<<dim3((M + 127) / 128, 2), 256, SMEM_GEMM>>>(b, M);

    // branch B (s2): fused merge + scan + CSR
    merge_mega_kernel<<<MEGA_BLOCKS, 256, 0, s2>>>(ei);
    scan1_kernel<<<SCAN_BLOCKS, 256, 0, s2>>>();
    scan2_kernel<<<1, 256, 0, s2>>>();
    scan3_kernel<<<SCAN_BLOCKS, 256, 0, s2>>>();
    fill_kernel<<<(EE + 255) / 256, 256, 0, s2>>>(ei);

    // join: stream 0 waits for branch B, then epilogue
    cudaEventRecord(evJoin, s2);
    cudaStreamWaitEvent(0, evJoin, 0);

    out_kernel<<<(NN * 32 + 255) / 256, 256>>>(out);

    int tail = out_size - NN * CC;
    if (tail > 0)
        tail_kernel<<<(tail + 255) / 256, 256>>>(out, out_size);
}